// round 1
// baseline (speedup 1.0000x reference)
#include <cuda_runtime.h>

// E3nnSimpleNodeBlock: out = TensorSquare(feats+msgs) with weights w000,w101,w110,w112
// N = 131072 nodes, MUL = 16. Output row = 144 floats: [out0(16) | out1(48) | out2(80)].
//
// Strategy (round 1): fp32 packed-pair (f32x2) compute. Each thread owns 2 nodes.
// Stage 1: s[v,w,c] = sum_u W[u,v,w] * x[u,c]  (x[u] in registers, weights pre-splatted in global scratch)
// Stage 2: contract s with x[v] (x[v] via conflict-free SMEM, dynamic v index).

#define T 128                 // threads per block
#define NODES_PER_BLOCK 256   // 2 nodes per thread
#define NNODES 131072

// Pre-splatted, pre-scaled weights: for each (v,w) pair (256), 64 slots
// [w000 u0..15 | w110 u0..15 | w101 u0..15 | w112 u0..15], each slot duplicated (splat f32x2).
// ulonglong2 element = 2 consecutive splatted weights. 256*32*16B = 128 KB.
__device__ ulonglong2 PW2[256 * 32];

// ---------- f32x2 helpers ----------
__device__ __forceinline__ unsigned long long f2fma(unsigned long long a, unsigned long long b,
                                                    unsigned long long c) {
    unsigned long long d;
    asm("fma.rn.f32x2 %0, %1, %2, %3;" : "=l"(d) : "l"(a), "l"(b), "l"(c));
    return d;
}
__device__ __forceinline__ unsigned long long f2add(unsigned long long a, unsigned long long b) {
    unsigned long long d;
    asm("add.rn.f32x2 %0, %1, %2;" : "=l"(d) : "l"(a), "l"(b));
    return d;
}
__device__ __forceinline__ unsigned long long f2mul(unsigned long long a, unsigned long long b) {
    unsigned long long d;
    asm("mul.rn.f32x2 %0, %1, %2;" : "=l"(d) : "l"(a), "l"(b));
    return d;
}
__device__ __forceinline__ unsigned long long fpack(float lo, float hi) {
    unsigned long long d;
    asm("mov.b64 %0, {%1, %2};" : "=l"(d) : "f"(lo), "f"(hi));
    return d;
}
__device__ __forceinline__ void funpack(unsigned long long p, float& lo, float& hi) {
    asm("mov.b64 {%0, %1}, %2;" : "=f"(lo), "=f"(hi) : "l"(p));
}

// ---------- weight prep: transpose + scale + splat ----------
__global__ void prep_kernel(const float* __restrict__ w000, const float* __restrict__ w101,
                            const float* __restrict__ w110, const float* __restrict__ w112) {
    int idx = blockIdx.x * blockDim.x + threadIdx.x;   // 0 .. 16383
    if (idx >= 256 * 64) return;
    int vw = idx >> 6, slot = idx & 63;
    int v = vw >> 4, w = vw & 15;
    int which = slot >> 4, u = slot & 15;
    int widx = u * 256 + v * 16 + w;                   // w[u][v][w], row-major
    const float A000 = 0.04419417382415922f;           // sqrt(1/(2*MUL*MUL))
    const float A110 = 0.02551551815399144f;           // A000/sqrt(3)
    const float A101 = 0.0625f;                        // sqrt(3/MUL^2)/sqrt(3) = 1/16
    const float A112 = 0.13975424859373686f;           // sqrt(5)/16
    float val;
    if (which == 0)      val = A000 * w000[widx];
    else if (which == 1) val = A110 * w110[widx];
    else if (which == 2) val = A101 * w101[widx];
    else                 val = A112 * w112[widx];
    reinterpret_cast<float2*>(PW2)[idx] = make_float2(val, val);   // splat
}

// ---------- main kernel ----------
__global__ __launch_bounds__(T) void e3nn_kernel(const float* __restrict__ feats,
                                                 const float* __restrict__ msgs,
                                                 float* __restrict__ out) {
    extern __shared__ ulonglong2 sx[];
    ulonglong2* xsa = sx;              // [16][T]  {px0[v], px1[v][0]}
    ulonglong2* xsb = sx + 16 * T;     // [16][T]  {px1[v][1], px1[v][2]}

    const int t = threadIdx.x;
    const int nA = blockIdx.x * NODES_PER_BLOCK + t;
    const int nB = nA + T;

    // ---- load x = feats + msgs for both nodes ----
    float xA[64], xB[64];
    {
        const float4* fA = reinterpret_cast<const float4*>(feats) + nA * 16;
        const float4* mA = reinterpret_cast<const float4*>(msgs) + nA * 16;
        const float4* fB = reinterpret_cast<const float4*>(feats) + nB * 16;
        const float4* mB = reinterpret_cast<const float4*>(msgs) + nB * 16;
#pragma unroll
        for (int q = 0; q < 16; ++q) {
            float4 f = fA[q], m = mA[q];
            xA[4 * q + 0] = f.x + m.x; xA[4 * q + 1] = f.y + m.y;
            xA[4 * q + 2] = f.z + m.z; xA[4 * q + 3] = f.w + m.w;
        }
#pragma unroll
        for (int q = 0; q < 16; ++q) {
            float4 f = fB[q], m = mB[q];
            xB[4 * q + 0] = f.x + m.x; xB[4 * q + 1] = f.y + m.y;
            xB[4 * q + 2] = f.z + m.z; xB[4 * q + 3] = f.w + m.w;
        }
    }

    // ---- pack node pair into f32x2 registers ----
    unsigned long long px0[16];      // x0[u]
    unsigned long long px1[16][3];   // x1[u][i] = x[16+3u+i]
#pragma unroll
    for (int u = 0; u < 16; ++u) px0[u] = fpack(xA[u], xB[u]);
#pragma unroll
    for (int u = 0; u < 16; ++u) {
#pragma unroll
        for (int i = 0; i < 3; ++i) px1[u][i] = fpack(xA[16 + 3 * u + i], xB[16 + 3 * u + i]);
    }

    // ---- stash for dynamic-v stage-2 access (thread-private; no sync needed) ----
#pragma unroll
    for (int v = 0; v < 16; ++v) {
        xsa[v * T + t] = make_ulonglong2(px0[v], px1[v][0]);
        xsb[v * T + t] = make_ulonglong2(px1[v][1], px1[v][2]);
    }

    float* outA = out + (long)nA * 144;
    float* outB = out + (long)nB * 144;

    const unsigned long long CS2  = fpack(0.31622776601683794f, 0.31622776601683794f); // 1/sqrt(10)
    const unsigned long long C62  = fpack(0.18257418583505536f, 0.18257418583505536f); // 1/sqrt(30)
    const unsigned long long NEG1 = fpack(-1.0f, -1.0f);
    const unsigned long long TWO2 = fpack(2.0f, 2.0f);

#pragma unroll 1
    for (int w = 0; w < 16; ++w) {
        unsigned long long acc00 = 0, acc01 = 0;              // out0 paths (000 / 110)
        unsigned long long a10 = 0, a11 = 0, a12 = 0;         // out1 k=0..2
        unsigned long long P0 = 0, P1 = 0, P2 = 0;            // out2 diagonal sums
        unsigned long long Q01 = 0, Q02 = 0, Q12 = 0;         // out2 cross sums

#pragma unroll 1
        for (int v = 0; v < 16; ++v) {
            const ulonglong2* __restrict__ pwv = PW2 + (v * 16 + w) * 32;

            unsigned long long s000a = 0, s000b = 0;
            unsigned long long s110_0 = 0, s110_1 = 0, s110_2 = 0;
            unsigned long long s101_0 = 0, s101_1 = 0, s101_2 = 0;
            unsigned long long s112_0 = 0, s112_1 = 0, s112_2 = 0;

#pragma unroll
            for (int g = 0; g < 8; ++g) {                     // w000
                ulonglong2 q = pwv[g];
                s000a = f2fma(q.x, px0[2 * g + 0], s000a);
                s000b = f2fma(q.y, px0[2 * g + 1], s000b);
            }
#pragma unroll
            for (int g = 0; g < 8; ++g) {                     // w110
                ulonglong2 q = pwv[8 + g];
                s110_0 = f2fma(q.x, px1[2 * g][0], s110_0);
                s110_1 = f2fma(q.x, px1[2 * g][1], s110_1);
                s110_2 = f2fma(q.x, px1[2 * g][2], s110_2);
                s110_0 = f2fma(q.y, px1[2 * g + 1][0], s110_0);
                s110_1 = f2fma(q.y, px1[2 * g + 1][1], s110_1);
                s110_2 = f2fma(q.y, px1[2 * g + 1][2], s110_2);
            }
#pragma unroll
            for (int g = 0; g < 8; ++g) {                     // w101
                ulonglong2 q = pwv[16 + g];
                s101_0 = f2fma(q.x, px1[2 * g][0], s101_0);
                s101_1 = f2fma(q.x, px1[2 * g][1], s101_1);
                s101_2 = f2fma(q.x, px1[2 * g][2], s101_2);
                s101_0 = f2fma(q.y, px1[2 * g + 1][0], s101_0);
                s101_1 = f2fma(q.y, px1[2 * g + 1][1], s101_1);
                s101_2 = f2fma(q.y, px1[2 * g + 1][2], s101_2);
            }
#pragma unroll
            for (int g = 0; g < 8; ++g) {                     // w112
                ulonglong2 q = pwv[24 + g];
                s112_0 = f2fma(q.x, px1[2 * g][0], s112_0);
                s112_1 = f2fma(q.x, px1[2 * g][1], s112_1);
                s112_2 = f2fma(q.x, px1[2 * g][2], s112_2);
                s112_0 = f2fma(q.y, px1[2 * g + 1][0], s112_0);
                s112_1 = f2fma(q.y, px1[2 * g + 1][1], s112_1);
                s112_2 = f2fma(q.y, px1[2 * g + 1][2], s112_2);
            }

            unsigned long long s000 = f2add(s000a, s000b);
            ulonglong2 xa = xsa[v * T + t];   // {x0[v], x1[v][0]}
            ulonglong2 xb = xsb[v * T + t];   // {x1[v][1], x1[v][2]}

            acc00 = f2fma(s000, xa.x, acc00);
            acc01 = f2fma(s110_0, xa.y, acc01);
            acc01 = f2fma(s110_1, xb.x, acc01);
            acc01 = f2fma(s110_2, xb.y, acc01);

            a10 = f2fma(s101_0, xa.x, a10);
            a11 = f2fma(s101_1, xa.x, a11);
            a12 = f2fma(s101_2, xa.x, a12);

            P0 = f2fma(s112_0, xa.y, P0);
            P1 = f2fma(s112_1, xb.x, P1);
            P2 = f2fma(s112_2, xb.y, P2);
            Q01 = f2fma(s112_0, xb.x, Q01);
            Q01 = f2fma(s112_1, xa.y, Q01);
            Q02 = f2fma(s112_0, xb.y, Q02);
            Q02 = f2fma(s112_2, xa.y, Q02);
            Q12 = f2fma(s112_1, xb.y, Q12);
            Q12 = f2fma(s112_2, xb.x, Q12);
        }

        // ---- epilogue for this w ----
        float a, b;
        funpack(f2add(acc00, acc01), a, b);
        outA[w] = a; outB[w] = b;

        funpack(a10, a, b); outA[16 + 3 * w + 0] = a; outB[16 + 3 * w + 0] = b;
        funpack(a11, a, b); outA[16 + 3 * w + 1] = a; outB[16 + 3 * w + 1] = b;
        funpack(a12, a, b); outA[16 + 3 * w + 2] = a; outB[16 + 3 * w + 2] = b;

        funpack(f2mul(CS2, Q01), a, b); outA[64 + 5 * w + 0] = a; outB[64 + 5 * w + 0] = b;
        funpack(f2mul(CS2, Q02), a, b); outA[64 + 5 * w + 1] = a; outB[64 + 5 * w + 1] = b;
        funpack(f2mul(CS2, Q12), a, b); outA[64 + 5 * w + 2] = a; outB[64 + 5 * w + 2] = b;

        unsigned long long d3 = f2fma(P1, NEG1, P0);                 // P0 - P1
        funpack(f2mul(CS2, d3), a, b); outA[64 + 5 * w + 3] = a; outB[64 + 5 * w + 3] = b;

        unsigned long long s01 = f2add(P0, P1);
        unsigned long long d4 = f2fma(TWO2, P2, f2mul(s01, NEG1));   // 2*P2 - P0 - P1
        funpack(f2mul(C62, d4), a, b); outA[64 + 5 * w + 4] = a; outB[64 + 5 * w + 4] = b;
    }
}

extern "C" void kernel_launch(void* const* d_in, const int* in_sizes, int n_in,
                              void* d_out, int out_size) {
    const float* feats = (const float*)d_in[0];
    const float* msgs  = (const float*)d_in[1];
    const float* w000  = (const float*)d_in[2];
    const float* w101  = (const float*)d_in[3];
    const float* w110  = (const float*)d_in[4];
    const float* w112  = (const float*)d_in[5];
    float* out = (float*)d_out;

    const int smem_bytes = 16 * T * 2 * (int)sizeof(ulonglong2);   // 64 KB
    cudaFuncSetAttribute(e3nn_kernel, cudaFuncAttributeMaxDynamicSharedMemorySize, smem_bytes);

    prep_kernel<<<64, 256>>>(w000, w101, w110, w112);
    e3nn_kernel<<<NNODES / NODES_PER_BLOCK, T, smem_bytes>>>(feats, msgs, out);
}

// round 2
// speedup vs baseline: 1.0018x; 1.0018x over previous
#include <cuda_runtime.h>

// E3nnSimpleNodeBlock: out = TensorSquare(feats+msgs) with weights w000,w101,w110,w112
// N = 131072 nodes, MUL = 16. Output row = 144 floats: [out0(16) | out1(48) | out2(80)].
//
// Strategy (round 1): fp32 packed-pair (f32x2) compute. Each thread owns 2 nodes.
// Stage 1: s[v,w,c] = sum_u W[u,v,w] * x[u,c]  (x[u] in registers, weights pre-splatted in global scratch)
// Stage 2: contract s with x[v] (x[v] via conflict-free SMEM, dynamic v index).

#define T 128                 // threads per block
#define NODES_PER_BLOCK 256   // 2 nodes per thread
#define NNODES 131072

// Pre-splatted, pre-scaled weights: for each (v,w) pair (256), 64 slots
// [w000 u0..15 | w110 u0..15 | w101 u0..15 | w112 u0..15], each slot duplicated (splat f32x2).
// ulonglong2 element = 2 consecutive splatted weights. 256*32*16B = 128 KB.
__device__ ulonglong2 PW2[256 * 32];

// ---------- f32x2 helpers ----------
__device__ __forceinline__ unsigned long long f2fma(unsigned long long a, unsigned long long b,
                                                    unsigned long long c) {
    unsigned long long d;
    asm("fma.rn.f32x2 %0, %1, %2, %3;" : "=l"(d) : "l"(a), "l"(b), "l"(c));
    return d;
}
__device__ __forceinline__ unsigned long long f2add(unsigned long long a, unsigned long long b) {
    unsigned long long d;
    asm("add.rn.f32x2 %0, %1, %2;" : "=l"(d) : "l"(a), "l"(b));
    return d;
}
__device__ __forceinline__ unsigned long long f2mul(unsigned long long a, unsigned long long b) {
    unsigned long long d;
    asm("mul.rn.f32x2 %0, %1, %2;" : "=l"(d) : "l"(a), "l"(b));
    return d;
}
__device__ __forceinline__ unsigned long long fpack(float lo, float hi) {
    unsigned long long d;
    asm("mov.b64 %0, {%1, %2};" : "=l"(d) : "f"(lo), "f"(hi));
    return d;
}
__device__ __forceinline__ void funpack(unsigned long long p, float& lo, float& hi) {
    asm("mov.b64 {%0, %1}, %2;" : "=f"(lo), "=f"(hi) : "l"(p));
}

// ---------- weight prep: transpose + scale + splat ----------
__global__ void prep_kernel(const float* __restrict__ w000, const float* __restrict__ w101,
                            const float* __restrict__ w110, const float* __restrict__ w112) {
    int idx = blockIdx.x * blockDim.x + threadIdx.x;   // 0 .. 16383
    if (idx >= 256 * 64) return;
    int vw = idx >> 6, slot = idx & 63;
    int v = vw >> 4, w = vw & 15;
    int which = slot >> 4, u = slot & 15;
    int widx = u * 256 + v * 16 + w;                   // w[u][v][w], row-major
    const float A000 = 0.04419417382415922f;           // sqrt(1/(2*MUL*MUL))
    const float A110 = 0.02551551815399144f;           // A000/sqrt(3)
    const float A101 = 0.0625f;                        // sqrt(3/MUL^2)/sqrt(3) = 1/16
    const float A112 = 0.13975424859373686f;           // sqrt(5)/16
    float val;
    if (which == 0)      val = A000 * w000[widx];
    else if (which == 1) val = A110 * w110[widx];
    else if (which == 2) val = A101 * w101[widx];
    else                 val = A112 * w112[widx];
    reinterpret_cast<float2*>(PW2)[idx] = make_float2(val, val);   // splat
}

// ---------- main kernel ----------
__global__ __launch_bounds__(T) void e3nn_kernel(const float* __restrict__ feats,
                                                 const float* __restrict__ msgs,
                                                 float* __restrict__ out) {
    extern __shared__ ulonglong2 sx[];
    ulonglong2* xsa = sx;              // [16][T]  {px0[v], px1[v][0]}
    ulonglong2* xsb = sx + 16 * T;     // [16][T]  {px1[v][1], px1[v][2]}

    const int t = threadIdx.x;
    const int nA = blockIdx.x * NODES_PER_BLOCK + t;
    const int nB = nA + T;

    // ---- load x = feats + msgs for both nodes ----
    float xA[64], xB[64];
    {
        const float4* fA = reinterpret_cast<const float4*>(feats) + nA * 16;
        const float4* mA = reinterpret_cast<const float4*>(msgs) + nA * 16;
        const float4* fB = reinterpret_cast<const float4*>(feats) + nB * 16;
        const float4* mB = reinterpret_cast<const float4*>(msgs) + nB * 16;
#pragma unroll
        for (int q = 0; q < 16; ++q) {
            float4 f = fA[q], m = mA[q];
            xA[4 * q + 0] = f.x + m.x; xA[4 * q + 1] = f.y + m.y;
            xA[4 * q + 2] = f.z + m.z; xA[4 * q + 3] = f.w + m.w;
        }
#pragma unroll
        for (int q = 0; q < 16; ++q) {
            float4 f = fB[q], m = mB[q];
            xB[4 * q + 0] = f.x + m.x; xB[4 * q + 1] = f.y + m.y;
            xB[4 * q + 2] = f.z + m.z; xB[4 * q + 3] = f.w + m.w;
        }
    }

    // ---- pack node pair into f32x2 registers ----
    unsigned long long px0[16];      // x0[u]
    unsigned long long px1[16][3];   // x1[u][i] = x[16+3u+i]
#pragma unroll
    for (int u = 0; u < 16; ++u) px0[u] = fpack(xA[u], xB[u]);
#pragma unroll
    for (int u = 0; u < 16; ++u) {
#pragma unroll
        for (int i = 0; i < 3; ++i) px1[u][i] = fpack(xA[16 + 3 * u + i], xB[16 + 3 * u + i]);
    }

    // ---- stash for dynamic-v stage-2 access (thread-private; no sync needed) ----
#pragma unroll
    for (int v = 0; v < 16; ++v) {
        xsa[v * T + t] = make_ulonglong2(px0[v], px1[v][0]);
        xsb[v * T + t] = make_ulonglong2(px1[v][1], px1[v][2]);
    }

    float* outA = out + (long)nA * 144;
    float* outB = out + (long)nB * 144;

    const unsigned long long CS2  = fpack(0.31622776601683794f, 0.31622776601683794f); // 1/sqrt(10)
    const unsigned long long C62  = fpack(0.18257418583505536f, 0.18257418583505536f); // 1/sqrt(30)
    const unsigned long long NEG1 = fpack(-1.0f, -1.0f);
    const unsigned long long TWO2 = fpack(2.0f, 2.0f);

#pragma unroll 1
    for (int w = 0; w < 16; ++w) {
        unsigned long long acc00 = 0, acc01 = 0;              // out0 paths (000 / 110)
        unsigned long long a10 = 0, a11 = 0, a12 = 0;         // out1 k=0..2
        unsigned long long P0 = 0, P1 = 0, P2 = 0;            // out2 diagonal sums
        unsigned long long Q01 = 0, Q02 = 0, Q12 = 0;         // out2 cross sums

#pragma unroll 1
        for (int v = 0; v < 16; ++v) {
            const ulonglong2* __restrict__ pwv = PW2 + (v * 16 + w) * 32;

            unsigned long long s000a = 0, s000b = 0;
            unsigned long long s110_0 = 0, s110_1 = 0, s110_2 = 0;
            unsigned long long s101_0 = 0, s101_1 = 0, s101_2 = 0;
            unsigned long long s112_0 = 0, s112_1 = 0, s112_2 = 0;

#pragma unroll
            for (int g = 0; g < 8; ++g) {                     // w000
                ulonglong2 q = pwv[g];
                s000a = f2fma(q.x, px0[2 * g + 0], s000a);
                s000b = f2fma(q.y, px0[2 * g + 1], s000b);
            }
#pragma unroll
            for (int g = 0; g < 8; ++g) {                     // w110
                ulonglong2 q = pwv[8 + g];
                s110_0 = f2fma(q.x, px1[2 * g][0], s110_0);
                s110_1 = f2fma(q.x, px1[2 * g][1], s110_1);
                s110_2 = f2fma(q.x, px1[2 * g][2], s110_2);
                s110_0 = f2fma(q.y, px1[2 * g + 1][0], s110_0);
                s110_1 = f2fma(q.y, px1[2 * g + 1][1], s110_1);
                s110_2 = f2fma(q.y, px1[2 * g + 1][2], s110_2);
            }
#pragma unroll
            for (int g = 0; g < 8; ++g) {                     // w101
                ulonglong2 q = pwv[16 + g];
                s101_0 = f2fma(q.x, px1[2 * g][0], s101_0);
                s101_1 = f2fma(q.x, px1[2 * g][1], s101_1);
                s101_2 = f2fma(q.x, px1[2 * g][2], s101_2);
                s101_0 = f2fma(q.y, px1[2 * g + 1][0], s101_0);
                s101_1 = f2fma(q.y, px1[2 * g + 1][1], s101_1);
                s101_2 = f2fma(q.y, px1[2 * g + 1][2], s101_2);
            }
#pragma unroll
            for (int g = 0; g < 8; ++g) {                     // w112
                ulonglong2 q = pwv[24 + g];
                s112_0 = f2fma(q.x, px1[2 * g][0], s112_0);
                s112_1 = f2fma(q.x, px1[2 * g][1], s112_1);
                s112_2 = f2fma(q.x, px1[2 * g][2], s112_2);
                s112_0 = f2fma(q.y, px1[2 * g + 1][0], s112_0);
                s112_1 = f2fma(q.y, px1[2 * g + 1][1], s112_1);
                s112_2 = f2fma(q.y, px1[2 * g + 1][2], s112_2);
            }

            unsigned long long s000 = f2add(s000a, s000b);
            ulonglong2 xa = xsa[v * T + t];   // {x0[v], x1[v][0]}
            ulonglong2 xb = xsb[v * T + t];   // {x1[v][1], x1[v][2]}

            acc00 = f2fma(s000, xa.x, acc00);
            acc01 = f2fma(s110_0, xa.y, acc01);
            acc01 = f2fma(s110_1, xb.x, acc01);
            acc01 = f2fma(s110_2, xb.y, acc01);

            a10 = f2fma(s101_0, xa.x, a10);
            a11 = f2fma(s101_1, xa.x, a11);
            a12 = f2fma(s101_2, xa.x, a12);

            P0 = f2fma(s112_0, xa.y, P0);
            P1 = f2fma(s112_1, xb.x, P1);
            P2 = f2fma(s112_2, xb.y, P2);
            Q01 = f2fma(s112_0, xb.x, Q01);
            Q01 = f2fma(s112_1, xa.y, Q01);
            Q02 = f2fma(s112_0, xb.y, Q02);
            Q02 = f2fma(s112_2, xa.y, Q02);
            Q12 = f2fma(s112_1, xb.y, Q12);
            Q12 = f2fma(s112_2, xb.x, Q12);
        }

        // ---- epilogue for this w ----
        float a, b;
        funpack(f2add(acc00, acc01), a, b);
        outA[w] = a; outB[w] = b;

        funpack(a10, a, b); outA[16 + 3 * w + 0] = a; outB[16 + 3 * w + 0] = b;
        funpack(a11, a, b); outA[16 + 3 * w + 1] = a; outB[16 + 3 * w + 1] = b;
        funpack(a12, a, b); outA[16 + 3 * w + 2] = a; outB[16 + 3 * w + 2] = b;

        funpack(f2mul(CS2, Q01), a, b); outA[64 + 5 * w + 0] = a; outB[64 + 5 * w + 0] = b;
        funpack(f2mul(CS2, Q02), a, b); outA[64 + 5 * w + 1] = a; outB[64 + 5 * w + 1] = b;
        funpack(f2mul(CS2, Q12), a, b); outA[64 + 5 * w + 2] = a; outB[64 + 5 * w + 2] = b;

        unsigned long long d3 = f2fma(P1, NEG1, P0);                 // P0 - P1
        funpack(f2mul(CS2, d3), a, b); outA[64 + 5 * w + 3] = a; outB[64 + 5 * w + 3] = b;

        unsigned long long s01 = f2add(P0, P1);
        unsigned long long d4 = f2fma(TWO2, P2, f2mul(s01, NEG1));   // 2*P2 - P0 - P1
        funpack(f2mul(C62, d4), a, b); outA[64 + 5 * w + 4] = a; outB[64 + 5 * w + 4] = b;
    }
}

extern "C" void kernel_launch(void* const* d_in, const int* in_sizes, int n_in,
                              void* d_out, int out_size) {
    const float* feats = (const float*)d_in[0];
    const float* msgs  = (const float*)d_in[1];
    const float* w000  = (const float*)d_in[2];
    const float* w101  = (const float*)d_in[3];
    const float* w110  = (const float*)d_in[4];
    const float* w112  = (const float*)d_in[5];
    float* out = (float*)d_out;

    const int smem_bytes = 16 * T * 2 * (int)sizeof(ulonglong2);   // 64 KB
    cudaFuncSetAttribute(e3nn_kernel, cudaFuncAttributeMaxDynamicSharedMemorySize, smem_bytes);

    prep_kernel<<<64, 256>>>(w000, w101, w110, w112);
    e3nn_kernel<<<NNODES / NODES_PER_BLOCK, T, smem_bytes>>>(feats, msgs, out);
}